// round 17
// baseline (speedup 1.0000x reference)
#include <cuda_runtime.h>
#include <cuda_bf16.h>
#include <cuda_fp16.h>
#include <cstdint>

// Problem constants
constexpr int Bn = 4, Tn = 256, Sn = 128, Fn = 256, Hn = 512, Vn = 1024;

// Scratch (allocation-free rule: __device__ globals)
__device__ float g_P[Bn * Tn * Hn];       // [b*T+t][h], includes b1
__device__ float g_Q[Bn * Sn * Hn];       // [b*S+s][h]
// W2 bf16 fragment order: [ck(16)][ntile(8)] x 512 uint4
__device__ uint4 g_W2f[16 * 8 * 512];
// A bf16 fragment order: [bt(1024)][ck(16)] x 512 uint4  (128 MB)
__device__ uint4 g_Af[(size_t)1024 * 16 * 512];
// fp16 logits (+b2) scratch; L2-resident per CTA in fused kernel
__device__ __half g_L[(size_t)Bn * Tn * Sn * Vn];

// ---------------------------------------------------------------------------
// helpers
// ---------------------------------------------------------------------------
__device__ __forceinline__ uint32_t packbf(float lo, float hi) {
    __nv_bfloat162 h = __floats2bfloat162_rn(lo, hi);   // lo -> low 16 bits
    return *reinterpret_cast<uint32_t*>(&h);
}

__device__ __forceinline__ uint32_t smem_u32(const void* p) {
    uint32_t a;
    asm("{ .reg .u64 t; cvta.to.shared.u64 t, %1; cvt.u32.u64 %0, t; }"
        : "=r"(a) : "l"(p));
    return a;
}

__device__ __forceinline__ void cp16(uint32_t smem_dst, const void* gmem_src) {
    asm volatile("cp.async.cg.shared.global [%0], [%1], 16;"
                 :: "r"(smem_dst), "l"(gmem_src));
}
__device__ __forceinline__ void cp_commit() {
    asm volatile("cp.async.commit_group;");
}
template <int N>
__device__ __forceinline__ void cp_wait() {
    asm volatile("cp.async.wait_group %0;" :: "n"(N));
}

__device__ __forceinline__ void mma_bf16(float (&c)[4], const uint32_t (&a)[4],
                                         uint32_t b0, uint32_t b1) {
    asm volatile(
        "mma.sync.aligned.m16n8k16.row.col.f32.bf16.bf16.f32 "
        "{%0,%1,%2,%3}, {%4,%5,%6,%7}, {%8,%9}, {%0,%1,%2,%3};"
        : "+f"(c[0]), "+f"(c[1]), "+f"(c[2]), "+f"(c[3])
        : "r"(a[0]), "r"(a[1]), "r"(a[2]), "r"(a[3]), "r"(b0), "r"(b1));
}

// ---------------------------------------------------------------------------
// Merged prep: blocks [0,64) do W2->g_W2f fragment pack; blocks [64,832) do
// the layer-1 projection (P and Q).
// ---------------------------------------------------------------------------
__global__ __launch_bounds__(256)
void prep_kernel(const float* __restrict__ src, const float* __restrict__ tgt,
                 const float* __restrict__ W1, const float* __restrict__ b1,
                 const float* __restrict__ W2) {
    const int bid = blockIdx.x;
    const int tid = threadIdx.x;

    if (bid < 64) {
        // ---- w2frag ----
        const int ck = bid >> 2;                      // 0..15
        const int n  = (bid & 3) * 256 + tid;         // 0..1023
        const int nt = n >> 7, wn = (n >> 6) & 1, j = (n >> 3) & 7, g = n & 7;
#pragma unroll
        for (int q = 0; q < 4; q++) {
            uint4 v;
            int k0 = ck * 32 + 2 * q;
            v.x = packbf(W2[(size_t)k0 * Vn + n],        W2[(size_t)(k0 + 1) * Vn + n]);
            v.y = packbf(W2[(size_t)(k0 + 8) * Vn + n],  W2[(size_t)(k0 + 9) * Vn + n]);
            v.z = packbf(W2[(size_t)(k0 + 16) * Vn + n], W2[(size_t)(k0 + 17) * Vn + n]);
            v.w = packbf(W2[(size_t)(k0 + 24) * Vn + n], W2[(size_t)(k0 + 25) * Vn + n]);
            g_W2f[(size_t)(ck * 8 + nt) * 512 + (wn * 8 + j) * 32 + 4 * g + q] = v;
        }
        return;
    }

    // ---- proj ----
    __shared__ float se[8][Fn];
    const int idx = bid - 64;                         // 0..767
    const int hy  = idx / 192;                        // 0..3
    const int rt  = idx - hy * 192;                   // 0..191
    const bool isP = rt < 128;
    const float* enc = isP ? src : tgt;
    float* dst = isP ? g_P : g_Q;
    const float* Wp = isP ? W1 : (W1 + Fn * Hn);
    const int row0 = (isP ? rt : rt - 128) * 8;

    for (int i = tid; i < 8 * Fn; i += 256)
        se[i >> 8][i & 255] = enc[(size_t)row0 * Fn + i];
    __syncthreads();

    const int h  = hy * 128 + (tid & 127);
    const int rh = tid >> 7;

    float acc[4] = {0.f, 0.f, 0.f, 0.f};
    const float* w = Wp + h;
    for (int f = 0; f < Fn; f++) {
        float wv = w[(size_t)f * Hn];
#pragma unroll
        for (int r = 0; r < 4; r++)
            acc[r] = fmaf(se[rh * 4 + r][f], wv, acc[r]);
    }
    const float bias = isP ? b1[h] : 0.f;
#pragma unroll
    for (int r = 0; r < 4; r++)
        dst[(size_t)(row0 + rh * 4 + r) * Hn + h] = acc[r] + bias;
}

// ---------------------------------------------------------------------------
// A-fragment materializer with 4-way t-batching (unchanged from R16).
// ---------------------------------------------------------------------------
__global__ __launch_bounds__(256)
void afrag_kernel() {
    __shared__ float sP[4][Hn];
    const int bt0 = blockIdx.x * 4;
    const int b   = bt0 >> 8;
    const int tid = threadIdx.x;

#pragma unroll
    for (int r = 0; r < 2; r++) {
        int i4 = tid + 256 * r;
        int tt = i4 >> 7, h4 = i4 & 127;
        ((float4*)sP[tt])[h4] =
            ((const float4*)(g_P + (size_t)(bt0 + tt) * Hn))[h4];
    }
    __syncthreads();

    const int wm = tid >> 6, ii = (tid >> 5) & 1;
    const int g = (tid >> 2) & 7, kki = (tid >> 1) & 1, qh = tid & 1;
    const int mtile = wm * 2 + ii;
    const int entry = mtile * 2 + kki;
    const int lt = 4 * g + 2 * qh;
    const int s_lo = mtile * 16 + g;
    const int ka_ = kki * 16 + qh * 4;
    const float* qlo = g_Q + (size_t)b * Sn * Hn + (size_t)s_lo * Hn + ka_;
    const float* qhi = qlo + 8 * Hn;

    float4 qv0 = *(const float4*)(qlo);
    float4 qv1 = *(const float4*)(qlo + 8);
    float4 qv2 = *(const float4*)(qhi);
    float4 qv3 = *(const float4*)(qhi + 8);

    for (int ck = 0; ck < 16; ck++) {
        const int k0 = ck * 32;
#pragma unroll
        for (int tt = 0; tt < 4; tt++) {
            float4 pa = *(const float4*)(sP[tt] + k0 + ka_);
            float4 pb = *(const float4*)(sP[tt] + k0 + ka_ + 8);
            uint4 u0, u1;
            u0.x = packbf(fmaxf(qv0.x + pa.x, 0.f), fmaxf(qv0.y + pa.y, 0.f));
            u0.y = packbf(fmaxf(qv2.x + pa.x, 0.f), fmaxf(qv2.y + pa.y, 0.f));
            u0.z = packbf(fmaxf(qv1.x + pb.x, 0.f), fmaxf(qv1.y + pb.y, 0.f));
            u0.w = packbf(fmaxf(qv3.x + pb.x, 0.f), fmaxf(qv3.y + pb.y, 0.f));
            u1.x = packbf(fmaxf(qv0.z + pa.z, 0.f), fmaxf(qv0.w + pa.w, 0.f));
            u1.y = packbf(fmaxf(qv2.z + pa.z, 0.f), fmaxf(qv2.w + pa.w, 0.f));
            u1.z = packbf(fmaxf(qv1.z + pb.z, 0.f), fmaxf(qv1.w + pb.w, 0.f));
            u1.w = packbf(fmaxf(qv3.z + pb.z, 0.f), fmaxf(qv3.w + pb.w, 0.f));
            uint4* dst = g_Af + (size_t)(bt0 + tt) * 8192 + ck * 512 + entry * 32;
            dst[lt]     = u0;
            dst[lt + 1] = u1;
        }
        if (ck < 15) {
            qv0 = *(const float4*)(qlo + k0 + 32);
            qv1 = *(const float4*)(qlo + k0 + 40);
            qv2 = *(const float4*)(qhi + k0 + 32);
            qv3 = *(const float4*)(qhi + k0 + 40);
        }
    }
}

// ---------------------------------------------------------------------------
// Fused GEMM + log_softmax. One CTA per bt owns all 8 n-tiles (128 rows x
// 1024 cols). Continuous 64-group pipeline (stage s: nt=s>>4, ck=s&15), 6
// buffers, one barrier per stage pair, odd stage barrier-free (R12 engine).
// Per n-chunk: online (max, expsum) per row via quad shuffles + 2-warp smem
// merge; fp16 logits(+b2) stored to g_L (default caching -> L2-resident).
// Final: lse from smem; re-read own g_L (L2-hot), write fp32 out (.cs).
// ---------------------------------------------------------------------------
constexpr uint32_t STAGE_U4 = 1024;           // uint4 per stage (A 512 + B 512)
constexpr uint32_t SMEM_DYN = 6 * STAGE_U4 * 16;   // 98304 B

__global__ __launch_bounds__(256, 2)
void joint_gemm_fused(float* __restrict__ out, const float* __restrict__ b2) {
    extern __shared__ uint4 sm4[];
    __shared__ float s_rm[128], s_rs[128];
    __shared__ float s_pm[2][128], s_ps[2][128];

    const int bt  = blockIdx.x;
    const int tid = threadIdx.x;
    const int wid = tid >> 5;
    const int lane = tid & 31;
    const int wm = wid & 3;                   // 32-row slice
    const int wn = wid >> 2;                  // 64-col slice
    const int gg = lane >> 2, tq = lane & 3;

    if (tid < 128) { s_rm[tid] = -1e30f; s_rs[tid] = 0.f; }

    const uint4* Asrc = g_Af + (size_t)bt * 8192;

    // stage s: nt = s>>4, ck = s&15
    auto fill = [&](int stage, int buf) {
        const int nt = stage >> 4, ck = stage & 15;
        uint32_t dst = smem_u32(sm4 + buf * STAGE_U4);
        const char* as = (const char*)(Asrc + (size_t)ck * 512);
        const char* bs = (const char*)(g_W2f + (size_t)(ck * 8 + nt) * 512);
#pragma unroll
        for (int r = 0; r < 2; r++) {
            int c = tid + 256 * r;
            cp16(dst + c * 16, as + c * 16);
            cp16(dst + 8192 + c * 16, bs + c * 16);
        }
    };
    auto issue_pair = [&](int gidx) {
        int buf = 2 * (gidx % 3);
        fill(2 * gidx, buf);
        fill(2 * gidx + 1, buf + 1);
        cp_commit();
    };

    issue_pair(0);
    issue_pair(1);

    float acc[2][8][4];
#pragma unroll
    for (int i = 0; i < 2; i++)
#pragma unroll
        for (int j = 0; j < 8; j++)
#pragma unroll
            for (int e = 0; e < 4; e++) acc[i][j][e] = 0.f;

    auto do_stage = [&](int buf) {
        const uint4* Ab = sm4 + buf * STAGE_U4;
        const uint4* Bb = Ab + 512 + (wn * 8) * 32;

        uint32_t a00[4], a01[4], a10[4], a11[4];
        *(uint4*)a00 = Ab[((wm * 2 + 0) * 2 + 0) * 32 + lane];
        *(uint4*)a01 = Ab[((wm * 2 + 0) * 2 + 1) * 32 + lane];
        *(uint4*)a10 = Ab[((wm * 2 + 1) * 2 + 0) * 32 + lane];
        *(uint4*)a11 = Ab[((wm * 2 + 1) * 2 + 1) * 32 + lane];

#pragma unroll
        for (int j = 0; j < 8; j++) {
            uint4 bv = Bb[j * 32 + lane];
            mma_bf16(acc[0][j], a00, bv.x, bv.y);
            mma_bf16(acc[0][j], a01, bv.z, bv.w);
            mma_bf16(acc[1][j], a10, bv.x, bv.y);
            mma_bf16(acc[1][j], a11, bv.z, bv.w);
        }
    };

    for (int g = 0; g < 64; g++) {
        if (g < 63) cp_wait<1>();
        else        cp_wait<0>();
        __syncthreads();

        const int bufe = 2 * (g % 3);
        do_stage(bufe);                       // even stage

        if (g < 62) issue_pair(g + 2);        // refills group g-1's buffers

        do_stage(bufe + 1);                   // odd stage (no wait, no barrier)

        if ((g & 7) == 7) {
            // ---- per-nt epilogue: store fp16 logits+b2, online softmax ----
            const int nt = g >> 3;
            const int colb = nt * 128 + wn * 64 + 2 * tq;
            float bb0[8], bb1[8];
#pragma unroll
            for (int j = 0; j < 8; j++) {
                float2 t = *(const float2*)(b2 + colb + 8 * j);
                bb0[j] = t.x; bb1[j] = t.y;
            }
#pragma unroll
            for (int i = 0; i < 2; i++) {
                const int r_lo = wm * 32 + i * 16 + gg;
                __half* pl0 = g_L + ((size_t)(bt * 128 + r_lo)) * Vn + colb;
                __half* pl1 = pl0 + 8 * Vn;
                float m0 = -1e30f, m1 = -1e30f;
#pragma unroll
                for (int j = 0; j < 8; j++) {
                    float x0 = acc[i][j][0] + bb0[j];
                    float x1 = acc[i][j][1] + bb1[j];
                    float x2 = acc[i][j][2] + bb0[j];
                    float x3 = acc[i][j][3] + bb1[j];
                    *(__half2*)(pl0 + 8 * j) = __floats2half2_rn(x0, x1);
                    *(__half2*)(pl1 + 8 * j) = __floats2half2_rn(x2, x3);
                    m0 = fmaxf(m0, fmaxf(x0, x1));
                    m1 = fmaxf(m1, fmaxf(x2, x3));
                }
#pragma unroll
                for (int o = 1; o <= 2; o <<= 1) {
                    m0 = fmaxf(m0, __shfl_xor_sync(0xffffffffu, m0, o));
                    m1 = fmaxf(m1, __shfl_xor_sync(0xffffffffu, m1, o));
                }
                float s0 = 0.f, s1 = 0.f;
#pragma unroll
                for (int j = 0; j < 8; j++) {
                    s0 += __expf(acc[i][j][0] + bb0[j] - m0)
                        + __expf(acc[i][j][1] + bb1[j] - m0);
                    s1 += __expf(acc[i][j][2] + bb0[j] - m1)
                        + __expf(acc[i][j][3] + bb1[j] - m1);
                }
#pragma unroll
                for (int o = 1; o <= 2; o <<= 1) {
                    s0 += __shfl_xor_sync(0xffffffffu, s0, o);
                    s1 += __shfl_xor_sync(0xffffffffu, s1, o);
                }
                if (tq == 0) {
                    s_pm[wn][r_lo]     = m0; s_ps[wn][r_lo]     = s0;
                    s_pm[wn][r_lo + 8] = m1; s_ps[wn][r_lo + 8] = s1;
                }
#pragma unroll
                for (int j = 0; j < 8; j++)
#pragma unroll
                    for (int e = 0; e < 4; e++) acc[i][j][e] = 0.f;
            }
            __syncthreads();
            if (tid < 128) {
                float m0 = s_pm[0][tid], m1 = s_pm[1][tid];
                float mn = fmaxf(m0, m1);
                float sc = s_ps[0][tid] * __expf(m0 - mn)
                         + s_ps[1][tid] * __expf(m1 - mn);
                float M = s_rm[tid], S = s_rs[tid];
                float mm = fmaxf(M, mn);
                s_rs[tid] = S * __expf(M - mm) + sc * __expf(mn - mm);
                s_rm[tid] = mm;
            }
            __syncthreads();
        }
    }

    // ---- finalize: lse, then readback L2-hot g_L and write fp32 out ----
    if (tid < 128) s_rm[tid] += logf(s_rs[tid]);
    __syncthreads();

    const __half* Lb = g_L + (size_t)bt * 128 * Vn;
    for (int rr = 0; rr < 16; rr++) {
        const int row = wid * 16 + rr;
        const float lse = s_rm[row];
        const uint4* pr = (const uint4*)(Lb + (size_t)row * Vn);
        float4* po = (float4*)(out + ((size_t)bt * 128 + row) * Vn);
#pragma unroll
        for (int i = 0; i < 4; i++) {
            uint4 u = pr[i * 32 + lane];
            float2 f0 = __half22float2(*(__half2*)&u.x);
            float2 f1 = __half22float2(*(__half2*)&u.y);
            float2 f2 = __half22float2(*(__half2*)&u.z);
            float2 f3 = __half22float2(*(__half2*)&u.w);
            __stcs(&po[(i * 32 + lane) * 2],
                   make_float4(f0.x - lse, f0.y - lse, f1.x - lse, f1.y - lse));
            __stcs(&po[(i * 32 + lane) * 2 + 1],
                   make_float4(f2.x - lse, f2.y - lse, f3.x - lse, f3.y - lse));
        }
    }
}

// ---------------------------------------------------------------------------
extern "C" void kernel_launch(void* const* d_in, const int* in_sizes, int n_in,
                              void* d_out, int out_size) {
    const float* src = (const float*)d_in[0];  // [B,T,F]
    const float* tgt = (const float*)d_in[1];  // [B,S,F]
    const float* W1  = (const float*)d_in[2];  // [2F,H]
    const float* b1  = (const float*)d_in[3];  // [H]
    const float* W2  = (const float*)d_in[4];  // [H,V]
    const float* b2  = (const float*)d_in[5];  // [V]
    float* out = (float*)d_out;                // [B,T,S,V]

    (void)in_sizes; (void)n_in; (void)out_size;

    cudaFuncSetAttribute(joint_gemm_fused,
                         cudaFuncAttributeMaxDynamicSharedMemorySize, SMEM_DYN);

    prep_kernel<<<832, 256>>>(src, tgt, W1, b1, W2);
    afrag_kernel<<<256, 256>>>();

    joint_gemm_fused<<<Bn * Tn * Tn / 256, 256, SMEM_DYN>>>(out, b2);
}